// round 3
// baseline (speedup 1.0000x reference)
#include <cuda_runtime.h>
#include <cuda_bf16.h>
#include <cstdint>
#include <math.h>

#define NN 50000
#define EE 1600000
#define GG 256
#define HH 128

// ---------------- scratch (static device allocations) ----------------
__device__ int   g_row[NN + 1];
__device__ int   g_col[EE];
__device__ int   g_fill[NN];
__device__ float g_deginv[NN];
__device__ float g_m [NN * HH];
__device__ float g_h1[NN * HH];
__device__ float g_h2[NN * HH];
__device__ float g_hb[NN * HH];
__device__ float g_pool[GG * 2 * HH];

__device__ __forceinline__ uint32_t smem_u32(const void* p) {
    uint32_t a;
    asm("{ .reg .u64 t; cvta.to.shared.u64 t, %1; cvt.u32.u64 %0, t; }" : "=r"(a) : "l"(p));
    return a;
}

// ---------------- utility kernels ----------------
__global__ void k_zero_int(int* p, int n) {
    int i = blockIdx.x * blockDim.x + threadIdx.x;
    if (i < n) p[i] = 0;
}
__global__ void k_zero_f(float* p, int n) {
    int i = blockIdx.x * blockDim.x + threadIdx.x;
    if (i < n) p[i] = 0.0f;
}
__global__ void k_count(const int* __restrict__ dst) {
    int e = blockIdx.x * blockDim.x + threadIdx.x;
    if (e < EE) atomicAdd(&g_fill[dst[e]], 1);
}
__global__ void k_scan() {
    __shared__ int ssum[1024];
    int t = threadIdx.x;
    const int C = (NN + 1023) / 1024;
    int s = t * C;
    int e = s + C; if (e > NN) e = NN;
    int loc = 0;
    for (int i = s; i < e; i++) loc += g_fill[i];
    ssum[t] = loc;
    __syncthreads();
    if (t == 0) {
        int run = 0;
        for (int i = 0; i < 1024; i++) { int v = ssum[i]; ssum[i] = run; run += v; }
        g_row[NN] = run;
    }
    __syncthreads();
    int run = ssum[t];
    for (int i = s; i < e; i++) {
        int c = g_fill[i];
        g_row[i]    = run;
        g_fill[i]   = run;
        g_deginv[i] = 1.0f / fmaxf((float)c, 1.0f);
        run += c;
    }
}
__global__ void k_fillcsr(const int* __restrict__ src, const int* __restrict__ dst) {
    int e = blockIdx.x * blockDim.x + threadIdx.x;
    if (e < EE) {
        int pos = atomicAdd(&g_fill[dst[e]], 1);
        g_col[pos] = src[e];
    }
}

// mean aggregation: one warp per dst node
__global__ void k_agg(const float* __restrict__ x) {
    int n = blockIdx.x * 8 + (threadIdx.x >> 5);
    if (n >= NN) return;
    int lane = threadIdx.x & 31;
    int s = g_row[n], e = g_row[n + 1];
    float4 acc = make_float4(0.f, 0.f, 0.f, 0.f);
    const float* xb = x + (size_t)lane * 4;
    #pragma unroll 4
    for (int i = s; i < e; i++) {
        int c = __ldg(&g_col[i]);
        float4 v = *(const float4*)(xb + (size_t)c * HH);
        acc.x += v.x; acc.y += v.y; acc.z += v.z; acc.w += v.w;
    }
    float d = g_deginv[n];
    acc.x *= d; acc.y *= d; acc.z *= d; acc.w *= d;
    *(float4*)(g_m + (size_t)n * HH + lane * 4) = acc;
}

// ---------------- bf16 mma.sync GEMM (3-term bf16 split) ----------------
// out = relu(A1@W1 + A2@W2 + bias); A* [NN,128] f32, W* [128,128] f32 row-major.
// A = Ah + Al (bf16 split); computes Ah*Wh + Al*Wh + Ah*Wl per pair.
// SMEM layout (bytes): sW[0,32768) sAh[32768,65536) sAl[65536,98304) bias[98304,98816)
static constexpr int SOFF_W  = 0;
static constexpr int SOFF_AH = 32768;
static constexpr int SOFF_AL = 65536;
static constexpr int SOFF_BI = 98304;
static constexpr int GEMM_SMEM = 98816;

// swizzled byte offset within a [rows x 256B] tile
__device__ __forceinline__ uint32_t swz(uint32_t row, uint32_t kbyte) {
    uint32_t col16 = kbyte >> 4;
    uint32_t scol = col16 ^ (row & 7);
    return row * 256 + scol * 16 + (kbyte & 15);
}

__device__ __forceinline__ void ldsm_x4(uint32_t* r, uint32_t addr) {
    asm volatile("ldmatrix.sync.aligned.m8n8.x4.shared.b16 {%0,%1,%2,%3}, [%4];"
                 : "=r"(r[0]), "=r"(r[1]), "=r"(r[2]), "=r"(r[3]) : "r"(addr));
}
__device__ __forceinline__ void ldsm_x4_t(uint32_t* r, uint32_t addr) {
    asm volatile("ldmatrix.sync.aligned.m8n8.x4.trans.shared.b16 {%0,%1,%2,%3}, [%4];"
                 : "=r"(r[0]), "=r"(r[1]), "=r"(r[2]), "=r"(r[3]) : "r"(addr));
}
__device__ __forceinline__ void mma16816(float* c, const uint32_t* a, uint32_t b0, uint32_t b1) {
    asm volatile(
        "mma.sync.aligned.m16n8k16.row.col.f32.bf16.bf16.f32 "
        "{%0,%1,%2,%3}, {%4,%5,%6,%7}, {%8,%9}, {%0,%1,%2,%3};"
        : "+f"(c[0]), "+f"(c[1]), "+f"(c[2]), "+f"(c[3])
        : "r"(a[0]), "r"(a[1]), "r"(a[2]), "r"(a[3]), "r"(b0), "r"(b1));
}

__device__ __forceinline__ uint32_t pack_bf2(float a, float b) {
    __nv_bfloat162 h = __floats2bfloat162_rn(a, b);
    return *(uint32_t*)&h;
}

__global__ __launch_bounds__(256, 2) void k_gemm_bf16(
    const float* __restrict__ A1, const float* __restrict__ W1,
    const float* __restrict__ A2, const float* __restrict__ W2,
    const float* __restrict__ bias, float* __restrict__ out)
{
    extern __shared__ char smem[];
    uint32_t sb = smem_u32(smem);
    int tid = threadIdx.x, lane = tid & 31, wid = tid >> 5;
    int wm = (wid & 3) * 32;   // warp m offset in tile
    int wn = (wid >> 2) * 64;  // warp n offset in tile
    int m0 = blockIdx.x * 128;

    float* sBias = (float*)(smem + SOFF_BI);
    if (tid < 128) sBias[tid] = bias[tid];

    float acc[2][8][4];
    #pragma unroll
    for (int a = 0; a < 2; a++)
        #pragma unroll
        for (int b = 0; b < 8; b++)
            #pragma unroll
            for (int c = 0; c < 4; c++) acc[a][b][c] = 0.f;

    // per-thread staging coords: row = tid>>1, half = tid&1 (64 floats)
    int strow = tid >> 1;
    int stkh  = (tid & 1) * 64;

    // per-thread ldmatrix coords
    // A: row = wm + mt*16 + (lane&15); kbyte = kt*32 + (lane>>4)*16
    uint32_t arow0 = (uint32_t)(wm + (lane & 15));
    uint32_t a_kadd = (uint32_t)((lane >> 4) * 16);
    // B: row = kt*16 + (lane&15); nbyte = (wn + bt*16)*2 + (lane>>4)*16
    uint32_t brow_l = (uint32_t)(lane & 15);
    uint32_t b_nadd = (uint32_t)((lane >> 4) * 16);

    #pragma unroll
    for (int p = 0; p < 2; p++) {
        const float* A = p ? A2 : A1;
        const float* W = p ? W2 : W1;

        __syncthreads();
        // ---- stage A hi/lo ----
        {
            int gr = m0 + strow; if (gr > NN - 1) gr = NN - 1;
            const float4* arow = (const float4*)(A + (size_t)gr * 128 + stkh);
            #pragma unroll
            for (int q = 0; q < 16; q++) {
                float4 v = arow[q];
                __nv_bfloat16 hx = __float2bfloat16_rn(v.x);
                __nv_bfloat16 hy = __float2bfloat16_rn(v.y);
                __nv_bfloat16 hz = __float2bfloat16_rn(v.z);
                __nv_bfloat16 hw = __float2bfloat16_rn(v.w);
                float lx = v.x - __bfloat162float(hx);
                float ly = v.y - __bfloat162float(hy);
                float lz = v.z - __bfloat162float(hz);
                float lw = v.w - __bfloat162float(hw);
                uint32_t kbyte = (uint32_t)(stkh * 2 + q * 8);
                uint32_t off = swz((uint32_t)strow, kbyte);
                uint32_t h01, h23;
                { __nv_bfloat162 t2 = {hx, hy}; h01 = *(uint32_t*)&t2; }
                { __nv_bfloat162 t2 = {hz, hw}; h23 = *(uint32_t*)&t2; }
                *(uint2*)(smem + SOFF_AH + off) = make_uint2(h01, h23);
                *(uint2*)(smem + SOFF_AL + off) =
                    make_uint2(pack_bf2(lx, ly), pack_bf2(lz, lw));
            }
        }
        // ---- stage W hi ----
        {
            const float4* wrow = (const float4*)(W + (size_t)strow * 128 + stkh);
            #pragma unroll
            for (int q = 0; q < 16; q++) {
                float4 v = wrow[q];
                uint32_t kbyte = (uint32_t)(stkh * 2 + q * 8);
                uint32_t off = swz((uint32_t)strow, kbyte);
                *(uint2*)(smem + SOFF_W + off) =
                    make_uint2(pack_bf2(v.x, v.y), pack_bf2(v.z, v.w));
            }
        }
        __syncthreads();

        // ---- passes 1 (Ah*Wh) and 2 (Al*Wh) ----
        #pragma unroll
        for (int pass = 0; pass < 2; pass++) {
            uint32_t abase = sb + (pass == 0 ? SOFF_AH : SOFF_AL);
            #pragma unroll
            for (int kt = 0; kt < 8; kt++) {
                uint32_t a0[4], a1[4];
                uint32_t kbA = (uint32_t)(kt * 32) + a_kadd;
                ldsm_x4(a0, abase + swz(arow0, kbA));
                ldsm_x4(a1, abase + swz(arow0 + 16, kbA));
                uint32_t brow = (uint32_t)(kt * 16) + brow_l;
                #pragma unroll
                for (int bt = 0; bt < 4; bt++) {
                    uint32_t b[4];
                    uint32_t nb = (uint32_t)((wn + bt * 16) * 2) + b_nadd;
                    ldsm_x4_t(b, sb + SOFF_W + swz(brow, nb));
                    mma16816(acc[0][bt * 2 + 0], a0, b[0], b[1]);
                    mma16816(acc[0][bt * 2 + 1], a0, b[2], b[3]);
                    mma16816(acc[1][bt * 2 + 0], a1, b[0], b[1]);
                    mma16816(acc[1][bt * 2 + 1], a1, b[2], b[3]);
                }
            }
        }
        __syncthreads();
        // ---- stage W lo ----
        {
            const float4* wrow = (const float4*)(W + (size_t)strow * 128 + stkh);
            #pragma unroll
            for (int q = 0; q < 16; q++) {
                float4 v = wrow[q];
                float lx = v.x - __bfloat162float(__float2bfloat16_rn(v.x));
                float ly = v.y - __bfloat162float(__float2bfloat16_rn(v.y));
                float lz = v.z - __bfloat162float(__float2bfloat16_rn(v.z));
                float lw = v.w - __bfloat162float(__float2bfloat16_rn(v.w));
                uint32_t kbyte = (uint32_t)(stkh * 2 + q * 8);
                uint32_t off = swz((uint32_t)strow, kbyte);
                *(uint2*)(smem + SOFF_W + off) =
                    make_uint2(pack_bf2(lx, ly), pack_bf2(lz, lw));
            }
        }
        __syncthreads();
        // ---- pass 3 (Ah*Wl) ----
        {
            uint32_t abase = sb + SOFF_AH;
            #pragma unroll
            for (int kt = 0; kt < 8; kt++) {
                uint32_t a0[4], a1[4];
                uint32_t kbA = (uint32_t)(kt * 32) + a_kadd;
                ldsm_x4(a0, abase + swz(arow0, kbA));
                ldsm_x4(a1, abase + swz(arow0 + 16, kbA));
                uint32_t brow = (uint32_t)(kt * 16) + brow_l;
                #pragma unroll
                for (int bt = 0; bt < 4; bt++) {
                    uint32_t b[4];
                    uint32_t nb = (uint32_t)((wn + bt * 16) * 2) + b_nadd;
                    ldsm_x4_t(b, sb + SOFF_W + swz(brow, nb));
                    mma16816(acc[0][bt * 2 + 0], a0, b[0], b[1]);
                    mma16816(acc[0][bt * 2 + 1], a0, b[2], b[3]);
                    mma16816(acc[1][bt * 2 + 0], a1, b[0], b[1]);
                    mma16816(acc[1][bt * 2 + 1], a1, b[2], b[3]);
                }
            }
        }
    }

    // ---- epilogue: bias + relu ----
    int g = lane >> 2, i2 = (lane & 3) * 2;
    #pragma unroll
    for (int mt = 0; mt < 2; mt++) {
        int r0 = m0 + wm + mt * 16 + g;
        int r1 = r0 + 8;
        #pragma unroll
        for (int nt = 0; nt < 8; nt++) {
            int col = wn + nt * 8 + i2;
            float b0 = sBias[col], b1 = sBias[col + 1];
            if (r0 < NN) {
                float2 v;
                v.x = fmaxf(acc[mt][nt][0] + b0, 0.f);
                v.y = fmaxf(acc[mt][nt][1] + b1, 0.f);
                *(float2*)(out + (size_t)r0 * 128 + col) = v;
            }
            if (r1 < NN) {
                float2 v;
                v.x = fmaxf(acc[mt][nt][2] + b0, 0.f);
                v.y = fmaxf(acc[mt][nt][3] + b1, 0.f);
                *(float2*)(out + (size_t)r1 * 128 + col) = v;
            }
        }
    }
}

// segment pool
__global__ void k_pool(const float* __restrict__ h, const int* __restrict__ batch, int off) {
    int idx = blockIdx.x * blockDim.x + threadIdx.x;
    int n = idx >> 5;
    if (n >= NN) return;
    int lane = idx & 31;
    int b = batch[n];
    float4 v = *(const float4*)(h + (size_t)n * 128 + lane * 4);
    float* p = g_pool + (size_t)b * 256 + off + lane * 4;
    atomicAdd(p + 0, v.x);
    atomicAdd(p + 1, v.y);
    atomicAdd(p + 2, v.z);
    atomicAdd(p + 3, v.w);
}

// head
__global__ void k_head(const float* __restrict__ gamma, const float* __restrict__ beta,
                       const float* __restrict__ rm, const float* __restrict__ rv,
                       const float* __restrict__ W1, const float* __restrict__ b1,
                       const float* __restrict__ W2, const float* __restrict__ b2,
                       float* __restrict__ out)
{
    __shared__ float sg[256];
    __shared__ float s1[128];
    __shared__ float s2[10];
    int g = blockIdx.x, t = threadIdx.x;  // 128 threads
    for (int i = t; i < 256; i += 128) {
        float v = g_pool[g * 256 + i];
        v = (v - rm[i]) * rsqrtf(rv[i] + 1e-5f) * gamma[i] + beta[i];
        sg[i] = v;
    }
    __syncthreads();
    float acc = b1[t];
    #pragma unroll 8
    for (int k = 0; k < 256; k++) acc += sg[k] * W1[k * 128 + t];
    s1[t] = fmaxf(acc, 0.f);
    __syncthreads();
    if (t < 10) {
        float a = b2[t];
        #pragma unroll 8
        for (int k = 0; k < 128; k++) a += s1[k] * W2[k * 10 + t];
        s2[t] = a;
    }
    __syncthreads();
    if (t == 0) {
        float m = s2[0];
        for (int j = 1; j < 10; j++) m = fmaxf(m, s2[j]);
        float ex[10]; float sum = 0.f;
        for (int j = 0; j < 10; j++) { ex[j] = expf(s2[j] - m); sum += ex[j]; }
        float inv = 1.0f / sum;
        for (int j = 0; j < 10; j++) out[g * 10 + j] = ex[j] * inv;
    }
}

// ---------------- host launch ----------------
extern "C" void kernel_launch(void* const* d_in, const int* in_sizes, int n_in,
                              void* d_out, int out_size)
{
    const float* x     = (const float*)d_in[0];
    const int*   ei    = (const int*)d_in[1];
    const int*   batch = (const int*)d_in[2];
    int base = (n_in > 3 && in_sizes[3] == 1) ? 4 : 3;

    const float* p[24];
    for (int i = 0; i < 24; i++) p[i] = (const float*)d_in[base + i];

    const int* src = ei;
    const int* dst = ei + EE;

    void *pm, *ph1, *ph2, *phb, *pfill, *ppool;
    cudaGetSymbolAddress(&pm,   g_m);
    cudaGetSymbolAddress(&ph1,  g_h1);
    cudaGetSymbolAddress(&ph2,  g_h2);
    cudaGetSymbolAddress(&phb,  g_hb);
    cudaGetSymbolAddress(&pfill, g_fill);
    cudaGetSymbolAddress(&ppool, g_pool);

    float* fm  = (float*)pm;
    float* fh1 = (float*)ph1;
    float* fh2 = (float*)ph2;
    float* fhb = (float*)phb;

    cudaFuncSetAttribute(k_gemm_bf16, cudaFuncAttributeMaxDynamicSharedMemorySize, GEMM_SMEM);

    const int ZB = 256;
    // ---- CSR build ----
    k_zero_int<<<(NN + ZB - 1) / ZB, ZB>>>((int*)pfill, NN);
    k_count<<<(EE + ZB - 1) / ZB, ZB>>>(dst);
    k_scan<<<1, 1024>>>();
    k_fillcsr<<<(EE + ZB - 1) / ZB, ZB>>>(src, dst);

    const int AGG_BLOCKS  = (NN + 7) / 8;
    const int GEMM_BLOCKS = (NN + 127) / 128;
    const int POOL_BLOCKS = (NN * 32 + ZB - 1) / ZB;

    // ---- block 0 ----
    k_agg<<<AGG_BLOCKS, 256>>>(x);
    k_gemm_bf16<<<GEMM_BLOCKS, 256, GEMM_SMEM>>>(fm, p[0], x, p[1], p[2], fh1);
    k_agg<<<AGG_BLOCKS, 256>>>(fh1);
    k_gemm_bf16<<<GEMM_BLOCKS, 256, GEMM_SMEM>>>(fm, p[3], fh1, p[4], p[5], fh2);
    k_gemm_bf16<<<GEMM_BLOCKS, 256, GEMM_SMEM>>>(fh1, p[6], fh2, p[6] + 128 * 128, p[7], fhb);

    // ---- pool 0 ----
    k_zero_f<<<(GG * 256 + ZB - 1) / ZB, ZB>>>((float*)ppool, GG * 256);
    k_pool<<<POOL_BLOCKS, ZB>>>(fhb, batch, 0);

    // ---- block 1 ----
    k_agg<<<AGG_BLOCKS, 256>>>(fhb);
    k_gemm_bf16<<<GEMM_BLOCKS, 256, GEMM_SMEM>>>(fm, p[8], fhb, p[9], p[10], fh1);
    k_agg<<<AGG_BLOCKS, 256>>>(fh1);
    k_gemm_bf16<<<GEMM_BLOCKS, 256, GEMM_SMEM>>>(fm, p[11], fh1, p[12], p[13], fh2);
    k_gemm_bf16<<<GEMM_BLOCKS, 256, GEMM_SMEM>>>(fh1, p[14], fh2, p[14] + 128 * 128, p[15], fm);

    // ---- pool 1 ----
    k_pool<<<POOL_BLOCKS, ZB>>>(fm, batch, 128);

    // ---- head ----
    k_head<<<GG, 128>>>(p[16], p[17], p[18], p[19], p[20], p[21], p[22], p[23],
                        (float*)d_out);
}

// round 4
// speedup vs baseline: 1.0589x; 1.0589x over previous
#include <cuda_runtime.h>
#include <cstdint>
#include <math.h>

#define NN 50000
#define EE 1600000
#define GG 256
#define HH 128

// ---------------- scratch (static device allocations) ----------------
__device__ int   g_row[NN + 1];
__device__ int   g_col[EE];
__device__ int   g_fill[NN];
__device__ float g_deginv[NN];
__device__ float g_h1[NN * HH];
__device__ float g_h2[NN * HH];
__device__ float g_hb[NN * HH];
__device__ float g_hc[NN * HH];
__device__ float g_pool[GG * 2 * HH];

// ---------------- utility kernels ----------------
__global__ void k_zero_int(int* p, int n) {
    int i = blockIdx.x * blockDim.x + threadIdx.x;
    if (i < n) p[i] = 0;
}
__global__ void k_zero_f(float* p, int n) {
    int i = blockIdx.x * blockDim.x + threadIdx.x;
    if (i < n) p[i] = 0.0f;
}
__global__ void k_count(const int* __restrict__ dst) {
    int e = blockIdx.x * blockDim.x + threadIdx.x;
    if (e < EE) atomicAdd(&g_fill[dst[e]], 1);
}
__global__ void k_scan() {
    __shared__ int ssum[1024];
    int t = threadIdx.x;
    const int C = (NN + 1023) / 1024;
    int s = t * C;
    int e = s + C; if (e > NN) e = NN;
    int loc = 0;
    for (int i = s; i < e; i++) loc += g_fill[i];
    ssum[t] = loc;
    __syncthreads();
    if (t == 0) {
        int run = 0;
        for (int i = 0; i < 1024; i++) { int v = ssum[i]; ssum[i] = run; run += v; }
        g_row[NN] = run;
    }
    __syncthreads();
    int run = ssum[t];
    for (int i = s; i < e; i++) {
        int c = g_fill[i];
        g_row[i]    = run;
        g_fill[i]   = run;
        g_deginv[i] = 1.0f / fmaxf((float)c, 1.0f);
        run += c;
    }
}
__global__ void k_fillcsr(const int* __restrict__ src, const int* __restrict__ dst) {
    int e = blockIdx.x * blockDim.x + threadIdx.x;
    if (e < EE) {
        int pos = atomicAdd(&g_fill[dst[e]], 1);
        g_col[pos] = src[e];
    }
}

// ---------------- fused SAGE kernel: (optional mean-agg) + 2-panel TF32 GEMM ----------------
// out = relu(A1 @ W1 + A2 @ W2 + bias)
//   panel1 A: if aggSrc != null -> mean over CSR neighbors of aggSrc rows; else direct A1dir
//   panel2 A: direct A2dir
// optional fused pool: if batch != null, atomicAdd(out row -> g_pool[batch[r]*256 + poolOff + col])
//
// SMEM: sA [128][132] f32(tf32 bits), sW [64][132] (K chunked in 2), bias[128]
static constexpr int SAP = 132;
static constexpr int OFF_W_F = 128 * SAP;            // in floats
static constexpr int OFF_B_F = 128 * SAP + 64 * SAP; // in floats
static constexpr int SAGE_SMEM = (128 * SAP + 64 * SAP + 128) * 4;

__device__ __forceinline__ uint32_t cvt_tf32(float f) {
    uint32_t r;
    asm("cvt.rna.tf32.f32 %0, %1;" : "=r"(r) : "f"(f));
    return r;
}

__device__ __forceinline__ void mma_tf32(float* c, const uint32_t* a, uint32_t b0, uint32_t b1) {
    asm volatile(
        "mma.sync.aligned.m16n8k8.row.col.f32.tf32.tf32.f32 "
        "{%0,%1,%2,%3}, {%4,%5,%6,%7}, {%8,%9}, {%0,%1,%2,%3};"
        : "+f"(c[0]), "+f"(c[1]), "+f"(c[2]), "+f"(c[3])
        : "r"(a[0]), "r"(a[1]), "r"(a[2]), "r"(a[3]), "r"(b0), "r"(b1));
}

__global__ __launch_bounds__(256, 2) void k_sage(
    const float* __restrict__ aggSrc,   // if non-null: gather source for panel 1
    const float* __restrict__ A1dir,    // if aggSrc null: direct panel-1 A
    const float* __restrict__ W1,
    const float* __restrict__ A2dir,
    const float* __restrict__ W2,
    const float* __restrict__ bias,
    float* __restrict__ out,
    const int* __restrict__ batch,      // if non-null: fused pool
    int poolOff)
{
    extern __shared__ float sm[];
    float*    sA = sm;
    uint32_t* sAu = (uint32_t*)sm;
    float*    sW = sm + OFF_W_F;
    uint32_t* sWu = (uint32_t*)sW;
    float*    sB = sm + OFF_B_F;

    int tid = threadIdx.x, lane = tid & 31, wid = tid >> 5;
    int wm = (wid & 3) * 32;   // warp m offset
    int wn = (wid >> 2) * 64;  // warp n offset
    int m0 = blockIdx.x * 128;
    int g = lane >> 2, tg = lane & 3;

    if (tid < 128) sB[tid] = bias[tid];

    float acc[2][8][4];
    #pragma unroll
    for (int a = 0; a < 2; a++)
        #pragma unroll
        for (int b = 0; b < 8; b++)
            #pragma unroll
            for (int c = 0; c < 4; c++) acc[a][b][c] = 0.f;

    #pragma unroll
    for (int p = 0; p < 2; p++) {
        const float* W = p ? W2 : W1;
        __syncthreads();   // previous panel's mma reads of sA/sW done

        // ---- fill sA ----
        if (p == 0 && aggSrc != nullptr) {
            // mean aggregation: warp handles 16 tile-rows
            #pragma unroll 1
            for (int i = 0; i < 16; i++) {
                int r = wid * 16 + i;
                int n = m0 + r; if (n > NN - 1) n = NN - 1;
                int s = g_row[n], e = g_row[n + 1];
                float4 a4 = make_float4(0.f, 0.f, 0.f, 0.f);
                const float* xb = aggSrc + (size_t)lane * 4;
                #pragma unroll 4
                for (int idx = s; idx < e; idx++) {
                    int c = __ldg(&g_col[idx]);
                    float4 v = *(const float4*)(xb + (size_t)c * HH);
                    a4.x += v.x; a4.y += v.y; a4.z += v.z; a4.w += v.w;
                }
                float d = g_deginv[n];
                uint32_t* dst = sAu + r * SAP + lane * 4;
                dst[0] = cvt_tf32(a4.x * d);
                dst[1] = cvt_tf32(a4.y * d);
                dst[2] = cvt_tf32(a4.z * d);
                dst[3] = cvt_tf32(a4.w * d);
            }
        } else {
            const float* A = p ? A2dir : A1dir;
            int r = tid >> 1;
            int half = (tid & 1) * 64;
            int gr = m0 + r; if (gr > NN - 1) gr = NN - 1;
            const float4* arow = (const float4*)(A + (size_t)gr * 128 + half);
            uint32_t* dst = sAu + r * SAP + half;
            #pragma unroll
            for (int q = 0; q < 16; q++) {
                float4 v = arow[q];
                dst[q * 4 + 0] = cvt_tf32(v.x);
                dst[q * 4 + 1] = cvt_tf32(v.y);
                dst[q * 4 + 2] = cvt_tf32(v.z);
                dst[q * 4 + 3] = cvt_tf32(v.w);
            }
        }

        // ---- two K chunks of 64 ----
        #pragma unroll
        for (int c = 0; c < 2; c++) {
            if (c == 1) __syncthreads();  // chunk0 mma done before overwriting sW
            // fill sW chunk: rows k 0..63 (global c*64+k), cols 0..127
            {
                int k = tid >> 2;
                int quarter = (tid & 3) * 32;
                const float4* wrow = (const float4*)(W + (size_t)(c * 64 + k) * 128 + quarter);
                uint32_t* dst = sWu + k * SAP + quarter;
                #pragma unroll
                for (int q = 0; q < 8; q++) {
                    float4 v = wrow[q];
                    dst[q * 4 + 0] = cvt_tf32(v.x);
                    dst[q * 4 + 1] = cvt_tf32(v.y);
                    dst[q * 4 + 2] = cvt_tf32(v.z);
                    dst[q * 4 + 3] = cvt_tf32(v.w);
                }
            }
            __syncthreads();

            // ---- mma over this chunk ----
            #pragma unroll
            for (int ks = 0; ks < 8; ks++) {
                int kA = c * 64 + ks * 8;
                uint32_t afr[2][4];
                #pragma unroll
                for (int mt = 0; mt < 2; mt++) {
                    int rbase = wm + mt * 16;
                    afr[mt][0] = sAu[(rbase + g) * SAP + kA + tg];
                    afr[mt][1] = sAu[(rbase + g + 8) * SAP + kA + tg];
                    afr[mt][2] = sAu[(rbase + g) * SAP + kA + tg + 4];
                    afr[mt][3] = sAu[(rbase + g + 8) * SAP + kA + tg + 4];
                }
                #pragma unroll
                for (int nt = 0; nt < 8; nt++) {
                    int nc = wn + nt * 8 + g;
                    uint32_t b0 = sWu[(ks * 8 + tg) * SAP + nc];
                    uint32_t b1 = sWu[(ks * 8 + tg + 4) * SAP + nc];
                    mma_tf32(acc[0][nt], afr[0], b0, b1);
                    mma_tf32(acc[1][nt], afr[1], b0, b1);
                }
            }
        }
    }

    // ---- epilogue: bias + relu (+ optional fused pool) ----
    #pragma unroll
    for (int mt = 0; mt < 2; mt++) {
        int r0 = m0 + wm + mt * 16 + g;
        int r1 = r0 + 8;
        int b0i = (r0 < NN && batch) ? batch[r0] : 0;
        int b1i = (r1 < NN && batch) ? batch[r1] : 0;
        #pragma unroll
        for (int nt = 0; nt < 8; nt++) {
            int col = wn + nt * 8 + tg * 2;
            float bb0 = sB[col], bb1 = sB[col + 1];
            if (r0 < NN) {
                float2 v;
                v.x = fmaxf(acc[mt][nt][0] + bb0, 0.f);
                v.y = fmaxf(acc[mt][nt][1] + bb1, 0.f);
                *(float2*)(out + (size_t)r0 * 128 + col) = v;
                if (batch) {
                    float* pp = g_pool + (size_t)b0i * 256 + poolOff + col;
                    atomicAdd(pp + 0, v.x);
                    atomicAdd(pp + 1, v.y);
                }
            }
            if (r1 < NN) {
                float2 v;
                v.x = fmaxf(acc[mt][nt][2] + bb0, 0.f);
                v.y = fmaxf(acc[mt][nt][3] + bb1, 0.f);
                *(float2*)(out + (size_t)r1 * 128 + col) = v;
                if (batch) {
                    float* pp = g_pool + (size_t)b1i * 256 + poolOff + col;
                    atomicAdd(pp + 0, v.x);
                    atomicAdd(pp + 1, v.y);
                }
            }
        }
    }
}

// head: BN + lin1(256->128)+relu + lin2(128->10) + softmax
__global__ void k_head(const float* __restrict__ gamma, const float* __restrict__ beta,
                       const float* __restrict__ rm, const float* __restrict__ rv,
                       const float* __restrict__ W1, const float* __restrict__ b1,
                       const float* __restrict__ W2, const float* __restrict__ b2,
                       float* __restrict__ out)
{
    __shared__ float sg[256];
    __shared__ float s1[128];
    __shared__ float s2[10];
    int gb = blockIdx.x, t = threadIdx.x;  // 128 threads
    for (int i = t; i < 256; i += 128) {
        float v = g_pool[gb * 256 + i];
        v = (v - rm[i]) * rsqrtf(rv[i] + 1e-5f) * gamma[i] + beta[i];
        sg[i] = v;
    }
    __syncthreads();
    float acc = b1[t];
    #pragma unroll 8
    for (int k = 0; k < 256; k++) acc += sg[k] * W1[k * 128 + t];
    s1[t] = fmaxf(acc, 0.f);
    __syncthreads();
    if (t < 10) {
        float a = b2[t];
        #pragma unroll 8
        for (int k = 0; k < 128; k++) a += s1[k] * W2[k * 10 + t];
        s2[t] = a;
    }
    __syncthreads();
    if (t == 0) {
        float m = s2[0];
        for (int j = 1; j < 10; j++) m = fmaxf(m, s2[j]);
        float ex[10]; float sum = 0.f;
        for (int j = 0; j < 10; j++) { ex[j] = expf(s2[j] - m); sum += ex[j]; }
        float inv = 1.0f / sum;
        for (int j = 0; j < 10; j++) out[gb * 10 + j] = ex[j] * inv;
    }
}

// ---------------- host launch ----------------
extern "C" void kernel_launch(void* const* d_in, const int* in_sizes, int n_in,
                              void* d_out, int out_size)
{
    const float* x     = (const float*)d_in[0];
    const int*   ei    = (const int*)d_in[1];
    const int*   batch = (const int*)d_in[2];
    int base = (n_in > 3 && in_sizes[3] == 1) ? 4 : 3;

    const float* p[24];
    for (int i = 0; i < 24; i++) p[i] = (const float*)d_in[base + i];
    // b0: 0..7 (Wl1,Wr1,b1,Wl2,Wr2,b2,Wlin,blin); b1: 8..15;
    // bn: 16..19; lin1: 20,21; lin2: 22,23

    const int* src = ei;
    const int* dst = ei + EE;

    void *ph1, *ph2, *phb, *phc, *pfill, *ppool;
    cudaGetSymbolAddress(&ph1,  g_h1);
    cudaGetSymbolAddress(&ph2,  g_h2);
    cudaGetSymbolAddress(&phb,  g_hb);
    cudaGetSymbolAddress(&phc,  g_hc);
    cudaGetSymbolAddress(&pfill, g_fill);
    cudaGetSymbolAddress(&ppool, g_pool);

    float* fh1 = (float*)ph1;
    float* fh2 = (float*)ph2;
    float* fhb = (float*)phb;
    float* fhc = (float*)phc;

    cudaFuncSetAttribute(k_sage, cudaFuncAttributeMaxDynamicSharedMemorySize, SAGE_SMEM);

    const int ZB = 256;
    // ---- CSR build ----
    k_zero_int<<<(NN + ZB - 1) / ZB, ZB>>>((int*)pfill, NN);
    k_count<<<(EE + ZB - 1) / ZB, ZB>>>(dst);
    k_scan<<<1, 1024>>>();
    k_fillcsr<<<(EE + ZB - 1) / ZB, ZB>>>(src, dst);
    k_zero_f<<<(GG * 256 + ZB - 1) / ZB, ZB>>>((float*)ppool, GG * 256);

    const int SB = (NN + 127) / 128;

    // ---- block 0 ----
    k_sage<<<SB, 256, SAGE_SMEM>>>(x,   nullptr, p[0], x,   p[1], p[2], fh1, nullptr, 0);
    k_sage<<<SB, 256, SAGE_SMEM>>>(fh1, nullptr, p[3], fh1, p[4], p[5], fh2, nullptr, 0);
    // JK linear + fused pool 0
    k_sage<<<SB, 256, SAGE_SMEM>>>(nullptr, fh1, p[6], fh2, p[6] + 128 * 128, p[7], fhb, batch, 0);

    // ---- block 1 ----
    k_sage<<<SB, 256, SAGE_SMEM>>>(fhb, nullptr, p[8],  fhb, p[9],  p[10], fh1, nullptr, 0);
    k_sage<<<SB, 256, SAGE_SMEM>>>(fh1, nullptr, p[11], fh1, p[12], p[13], fh2, nullptr, 0);
    // JK linear + fused pool 1
    k_sage<<<SB, 256, SAGE_SMEM>>>(nullptr, fh1, p[14], fh2, p[14] + 128 * 128, p[15], fhc, batch, 128);

    // ---- head ----
    k_head<<<GG, 128>>>(p[16], p[17], p[18], p[19], p[20], p[21], p[22], p[23],
                        (float*)d_out);
}

// round 5
// speedup vs baseline: 1.1307x; 1.0678x over previous
#include <cuda_runtime.h>
#include <cuda_bf16.h>
#include <cstdint>
#include <math.h>

#define NN 50000
#define EE 1600000
#define GG 256
#define HH 128
#define NGB 391   // GEMM blocks (ceil(50000/128))

// ---------------- scratch ----------------
__device__ int   g_row[NN + 1];
__device__ int   g_col[EE];
__device__ int   g_fill[NN];
__device__ float g_deginv[NN];
__device__ float g_m [NN * HH];
__device__ float g_t [NN * HH];
__device__ float g_h1[NN * HH];
__device__ float g_h2[NN * HH];
__device__ float g_hb[NN * HH];
__device__ float g_hc[NN * HH];
__device__ float g_pool[GG * 2 * HH];
// 12 weight slots of 128x128, bf16 hi/lo
__device__ __align__(16) __nv_bfloat16 g_Wh[12 * 16384];
__device__ __align__(16) __nv_bfloat16 g_Wl[12 * 16384];

__device__ __forceinline__ uint32_t smem_u32(const void* p) {
    uint32_t a;
    asm("{ .reg .u64 t; cvta.to.shared.u64 t, %1; cvt.u32.u64 %0, t; }" : "=r"(a) : "l"(p));
    return a;
}

// ---------------- utility kernels ----------------
__global__ void k_zero_int(int* p, int n) {
    int i = blockIdx.x * blockDim.x + threadIdx.x;
    if (i < n) p[i] = 0;
}
__global__ void k_zero_f(float* p, int n) {
    int i = blockIdx.x * blockDim.x + threadIdx.x;
    if (i < n) p[i] = 0.0f;
}
__global__ void k_count(const int* __restrict__ dst) {
    int e = blockIdx.x * blockDim.x + threadIdx.x;
    if (e < EE) atomicAdd(&g_fill[dst[e]], 1);
}
__global__ void k_scan() {
    __shared__ int ssum[1024];
    int t = threadIdx.x;
    const int C = (NN + 1023) / 1024;
    int s = t * C;
    int e = s + C; if (e > NN) e = NN;
    int loc = 0;
    for (int i = s; i < e; i++) loc += g_fill[i];
    ssum[t] = loc;
    __syncthreads();
    if (t == 0) {
        int run = 0;
        for (int i = 0; i < 1024; i++) { int v = ssum[i]; ssum[i] = run; run += v; }
        g_row[NN] = run;
    }
    __syncthreads();
    int run = ssum[t];
    for (int i = s; i < e; i++) {
        int c = g_fill[i];
        g_row[i]    = run;
        g_fill[i]   = run;
        g_deginv[i] = 1.0f / fmaxf((float)c, 1.0f);
        run += c;
    }
}
__global__ void k_fillcsr(const int* __restrict__ src, const int* __restrict__ dst) {
    int e = blockIdx.x * blockDim.x + threadIdx.x;
    if (e < EE) {
        int pos = atomicAdd(&g_fill[dst[e]], 1);
        g_col[pos] = src[e];
    }
}

// ---------------- weight conversion: fp32 -> bf16 hi/lo, 12 slots ----------------
__global__ void k_wconv(const float* s0, const float* s1, const float* s2, const float* s3,
                        const float* s4, const float* s5, const float* s6, const float* s7,
                        const float* s8, const float* s9, const float* s10, const float* s11)
{
    int idx = blockIdx.x * 256 + threadIdx.x;   // 12*16384 total
    int slot = idx >> 14;
    int w = idx & 16383;
    const float* src;
    switch (slot) {
        case 0: src = s0; break; case 1: src = s1; break;
        case 2: src = s2; break; case 3: src = s3; break;
        case 4: src = s4; break; case 5: src = s5; break;
        case 6: src = s6; break; case 7: src = s7; break;
        case 8: src = s8; break; case 9: src = s9; break;
        case 10: src = s10; break; default: src = s11; break;
    }
    float v = src[w];
    __nv_bfloat16 h = __float2bfloat16_rn(v);
    g_Wh[idx] = h;
    g_Wl[idx] = __float2bfloat16_rn(v - __bfloat162float(h));
}

// ---------------- bf16 3-term GEMM core ----------------
// SMEM: A tile 128 rows x 256B (Ah bytes 0-127 | Al 128-255 per row, swizzled)
//       Wh 64 rows x 256B, Wl 64 rows x 256B, bias 512B
static constexpr int OFF_A  = 0;
static constexpr int OFF_WH = 32768;
static constexpr int OFF_WL = 49152;
static constexpr int OFF_BI = 65536;
static constexpr int GEMM_SMEM = 66048;

__device__ __forceinline__ uint32_t swz(uint32_t row, uint32_t kbyte) {
    uint32_t col16 = kbyte >> 4;
    uint32_t scol = col16 ^ (row & 7);
    return row * 256 + scol * 16 + (kbyte & 15);
}
__device__ __forceinline__ void ldsm_x4(uint32_t* r, uint32_t addr) {
    asm volatile("ldmatrix.sync.aligned.m8n8.x4.shared.b16 {%0,%1,%2,%3}, [%4];"
                 : "=r"(r[0]), "=r"(r[1]), "=r"(r[2]), "=r"(r[3]) : "r"(addr));
}
__device__ __forceinline__ void ldsm_x4_t(uint32_t* r, uint32_t addr) {
    asm volatile("ldmatrix.sync.aligned.m8n8.x4.trans.shared.b16 {%0,%1,%2,%3}, [%4];"
                 : "=r"(r[0]), "=r"(r[1]), "=r"(r[2]), "=r"(r[3]) : "r"(addr));
}
__device__ __forceinline__ void mma16816(float* c, const uint32_t* a, uint32_t b0, uint32_t b1) {
    asm volatile(
        "mma.sync.aligned.m16n8k16.row.col.f32.bf16.bf16.f32 "
        "{%0,%1,%2,%3}, {%4,%5,%6,%7}, {%8,%9}, {%0,%1,%2,%3};"
        : "+f"(c[0]), "+f"(c[1]), "+f"(c[2]), "+f"(c[3])
        : "r"(a[0]), "r"(a[1]), "r"(a[2]), "r"(a[3]), "r"(b0), "r"(b1));
}
__device__ __forceinline__ uint32_t bf2(float a, float b) {
    __nv_bfloat162 t = __floats2bfloat162_rn(a, b);
    return *(uint32_t*)&t;
}

__device__ __forceinline__ void gemm_tile(
    const float* A1, int slot1, const float* A2, int slot2,
    const float* bias, const float* preact, bool doRelu,
    float* out, const int* batch, int poolOff,
    int m0, char* smem, uint32_t sb)
{
    int tid = threadIdx.x, lane = tid & 31, wid = tid >> 5;
    int wm = (wid & 3) * 32;
    int wn = (wid >> 2) * 64;
    float* sB = (float*)(smem + OFF_BI);
    if (bias && tid < 128) sB[tid] = bias[tid];

    float acc[2][8][4];
    #pragma unroll
    for (int a = 0; a < 2; a++)
        #pragma unroll
        for (int b = 0; b < 8; b++)
            #pragma unroll
            for (int c = 0; c < 4; c++) acc[a][b][c] = 0.f;

    int nP = (A2 != nullptr) ? 2 : 1;
    uint32_t aRow = (uint32_t)(wm + (lane & 15));
    uint32_t aKadd = (uint32_t)((lane >> 4) * 16);
    uint32_t wRowL = (uint32_t)(lane & 15);
    uint32_t nAdd = (uint32_t)((lane >> 4) * 16);

    for (int p = 0; p < nP; p++) {
        const float* A = p ? A2 : A1;
        int slot = p ? slot2 : slot1;
        const __nv_bfloat16* wh = g_Wh + slot * 16384;
        const __nv_bfloat16* wl = g_Wl + slot * 16384;

        #pragma unroll
        for (int c = 0; c < 2; c++) {
            __syncthreads();
            // ---- stage A chunk (rows 128 x k64, hi/lo) ----
            {
                int r = tid >> 1, half = tid & 1;
                int gr = m0 + r; if (gr > NN - 1) gr = NN - 1;
                const float4* ap = (const float4*)(A + (size_t)gr * 128 + c * 64 + half * 32);
                #pragma unroll
                for (int q = 0; q < 8; q++) {
                    float4 v = ap[q];
                    __nv_bfloat16 hx = __float2bfloat16_rn(v.x);
                    __nv_bfloat16 hy = __float2bfloat16_rn(v.y);
                    __nv_bfloat16 hz = __float2bfloat16_rn(v.z);
                    __nv_bfloat16 hw = __float2bfloat16_rn(v.w);
                    uint32_t h01, h23;
                    { __nv_bfloat162 t2 = {hx, hy}; h01 = *(uint32_t*)&t2; }
                    { __nv_bfloat162 t2 = {hz, hw}; h23 = *(uint32_t*)&t2; }
                    float lx = v.x - __bfloat162float(hx);
                    float ly = v.y - __bfloat162float(hy);
                    float lz = v.z - __bfloat162float(hz);
                    float lw = v.w - __bfloat162float(hw);
                    uint32_t kb = (uint32_t)(half * 64 + q * 8);
                    *(uint2*)(smem + OFF_A + swz((uint32_t)r, kb)) = make_uint2(h01, h23);
                    *(uint2*)(smem + OFF_A + swz((uint32_t)r, kb + 128)) =
                        make_uint2(bf2(lx, ly), bf2(lz, lw));
                }
            }
            // ---- stage W chunk (64 k-rows x 128 n, hi + lo) ----
            {
                int k = tid >> 2, q4 = tid & 3;
                const uint4* whp = (const uint4*)(wh + (size_t)(c * 64 + k) * 128 + q4 * 32);
                const uint4* wlp = (const uint4*)(wl + (size_t)(c * 64 + k) * 128 + q4 * 32);
                #pragma unroll
                for (int q = 0; q < 4; q++) {
                    uint32_t b = (uint32_t)(q4 * 64 + q * 16);
                    *(uint4*)(smem + OFF_WH + swz((uint32_t)k, b)) = whp[q];
                    *(uint4*)(smem + OFF_WL + swz((uint32_t)k, b)) = wlp[q];
                }
            }
            __syncthreads();

            // ---- mma: 4 k16-tiles per chunk, merged 3-term ----
            #pragma unroll
            for (int ks = 0; ks < 4; ks++) {
                uint32_t kb = (uint32_t)(ks * 32) + aKadd;
                uint32_t ah0[4], ah1[4], al0[4], al1[4];
                ldsm_x4(ah0, sb + OFF_A + swz(aRow, kb));
                ldsm_x4(ah1, sb + OFF_A + swz(aRow + 16, kb));
                ldsm_x4(al0, sb + OFF_A + swz(aRow, kb + 128));
                ldsm_x4(al1, sb + OFF_A + swz(aRow + 16, kb + 128));
                uint32_t wRow = (uint32_t)(ks * 16) + wRowL;
                #pragma unroll
                for (int bt = 0; bt < 4; bt++) {
                    uint32_t nb = (uint32_t)((wn + bt * 16) * 2) + nAdd;
                    uint32_t bh[4], bl[4];
                    ldsm_x4_t(bh, sb + OFF_WH + swz(wRow, nb));
                    mma16816(acc[0][bt * 2 + 0], ah0, bh[0], bh[1]);
                    mma16816(acc[0][bt * 2 + 1], ah0, bh[2], bh[3]);
                    mma16816(acc[1][bt * 2 + 0], ah1, bh[0], bh[1]);
                    mma16816(acc[1][bt * 2 + 1], ah1, bh[2], bh[3]);
                    mma16816(acc[0][bt * 2 + 0], al0, bh[0], bh[1]);
                    mma16816(acc[0][bt * 2 + 1], al0, bh[2], bh[3]);
                    mma16816(acc[1][bt * 2 + 0], al1, bh[0], bh[1]);
                    mma16816(acc[1][bt * 2 + 1], al1, bh[2], bh[3]);
                    ldsm_x4_t(bl, sb + OFF_WL + swz(wRow, nb));
                    mma16816(acc[0][bt * 2 + 0], ah0, bl[0], bl[1]);
                    mma16816(acc[0][bt * 2 + 1], ah0, bl[2], bl[3]);
                    mma16816(acc[1][bt * 2 + 0], ah1, bl[0], bl[1]);
                    mma16816(acc[1][bt * 2 + 1], ah1, bl[2], bl[3]);
                }
            }
        }
    }

    // ---- epilogue ----
    int g = lane >> 2, tg = lane & 3;
    #pragma unroll
    for (int mt = 0; mt < 2; mt++) {
        int r0 = m0 + wm + mt * 16 + g;
        int r1 = r0 + 8;
        int b0i = (batch && r0 < NN) ? batch[r0] : 0;
        int b1i = (batch && r1 < NN) ? batch[r1] : 0;
        #pragma unroll
        for (int nt = 0; nt < 8; nt++) {
            int col = wn + nt * 8 + tg * 2;
            float bb0 = bias ? sB[col] : 0.f;
            float bb1 = bias ? sB[col + 1] : 0.f;
            if (r0 < NN) {
                float2 v = make_float2(acc[mt][nt][0] + bb0, acc[mt][nt][1] + bb1);
                if (preact) {
                    float2 pv = *(const float2*)(preact + (size_t)r0 * 128 + col);
                    v.x += pv.x; v.y += pv.y;
                }
                if (doRelu) { v.x = fmaxf(v.x, 0.f); v.y = fmaxf(v.y, 0.f); }
                *(float2*)(out + (size_t)r0 * 128 + col) = v;
                if (batch) {
                    float* pp = g_pool + (size_t)b0i * 256 + poolOff + col;
                    atomicAdd(pp + 0, v.x);
                    atomicAdd(pp + 1, v.y);
                }
            }
            if (r1 < NN) {
                float2 v = make_float2(acc[mt][nt][2] + bb0, acc[mt][nt][3] + bb1);
                if (preact) {
                    float2 pv = *(const float2*)(preact + (size_t)r1 * 128 + col);
                    v.x += pv.x; v.y += pv.y;
                }
                if (doRelu) { v.x = fmaxf(v.x, 0.f); v.y = fmaxf(v.y, 0.f); }
                *(float2*)(out + (size_t)r1 * 128 + col) = v;
                if (batch) {
                    float* pp = g_pool + (size_t)b1i * 256 + poolOff + col;
                    atomicAdd(pp + 0, v.x);
                    atomicAdd(pp + 1, v.y);
                }
            }
        }
    }
}

// ---------------- co-scheduled kernel: agg blocks + P2 GEMM blocks ----------------
// gemm blocks at bid % 17 == 0 (391 of them); rest are agg blocks (6250).
__global__ __launch_bounds__(256, 2) void k_combo(
    const float* __restrict__ in, int slotR, const float* __restrict__ bias,
    float* __restrict__ outPre)
{
    extern __shared__ char smem[];
    int bid = blockIdx.x;
    int g17 = bid / 17, r17 = bid % 17;
    if (r17 == 0 && g17 < NGB) {
        gemm_tile(in, slotR, nullptr, -1, bias, nullptr, false,
                  outPre, nullptr, 0, g17 * 128, smem, smem_u32(smem));
    } else {
        int pre = g17 + 1; if (pre > NGB) pre = NGB;
        int aid = bid - pre;
        int wid = threadIdx.x >> 5, lane = threadIdx.x & 31;
        int n = aid * 8 + wid;
        if (n >= NN) return;
        int s = g_row[n], e = g_row[n + 1];
        float4 a4 = make_float4(0.f, 0.f, 0.f, 0.f);
        const float* xb = in + (size_t)lane * 4;
        #pragma unroll 4
        for (int i = s; i < e; i++) {
            int c = __ldg(&g_col[i]);
            float4 v = *(const float4*)(xb + (size_t)c * HH);
            a4.x += v.x; a4.y += v.y; a4.z += v.z; a4.w += v.w;
        }
        float d = g_deginv[n];
        a4.x *= d; a4.y *= d; a4.z *= d; a4.w *= d;
        *(float4*)(g_m + (size_t)n * HH + lane * 4) = a4;
    }
}

// single-panel GEMM: out = relu(A@slot + preact)
__global__ __launch_bounds__(256, 2) void k_gemm1(
    const float* __restrict__ A, int slotL, const float* __restrict__ preact,
    float* __restrict__ out)
{
    extern __shared__ char smem[];
    gemm_tile(A, slotL, nullptr, -1, nullptr, preact, true,
              out, nullptr, 0, blockIdx.x * 128, smem, smem_u32(smem));
}

// JK: out = relu(A1@s1 + A2@s2 + bias), fused pool
__global__ __launch_bounds__(256, 2) void k_gemmJK(
    const float* __restrict__ A1, int s1, const float* __restrict__ A2, int s2,
    const float* __restrict__ bias, float* __restrict__ out,
    const int* __restrict__ batch, int poolOff)
{
    extern __shared__ char smem[];
    gemm_tile(A1, s1, A2, s2, bias, nullptr, true,
              out, batch, poolOff, blockIdx.x * 128, smem, smem_u32(smem));
}

// ---------------- head ----------------
__global__ void k_head(const float* __restrict__ gamma, const float* __restrict__ beta,
                       const float* __restrict__ rm, const float* __restrict__ rv,
                       const float* __restrict__ W1, const float* __restrict__ b1,
                       const float* __restrict__ W2, const float* __restrict__ b2,
                       float* __restrict__ out)
{
    __shared__ float sg[256];
    __shared__ float s1[128];
    __shared__ float s2[10];
    int gb = blockIdx.x, t = threadIdx.x;
    for (int i = t; i < 256; i += 128) {
        float v = g_pool[gb * 256 + i];
        v = (v - rm[i]) * rsqrtf(rv[i] + 1e-5f) * gamma[i] + beta[i];
        sg[i] = v;
    }
    __syncthreads();
    float acc = b1[t];
    #pragma unroll 8
    for (int k = 0; k < 256; k++) acc += sg[k] * W1[k * 128 + t];
    s1[t] = fmaxf(acc, 0.f);
    __syncthreads();
    if (t < 10) {
        float a = b2[t];
        #pragma unroll 8
        for (int k = 0; k < 128; k++) a += s1[k] * W2[k * 10 + t];
        s2[t] = a;
    }
    __syncthreads();
    if (t == 0) {
        float m = s2[0];
        for (int j = 1; j < 10; j++) m = fmaxf(m, s2[j]);
        float ex[10]; float sum = 0.f;
        for (int j = 0; j < 10; j++) { ex[j] = expf(s2[j] - m); sum += ex[j]; }
        float inv = 1.0f / sum;
        for (int j = 0; j < 10; j++) out[gb * 10 + j] = ex[j] * inv;
    }
}

// ---------------- host launch ----------------
extern "C" void kernel_launch(void* const* d_in, const int* in_sizes, int n_in,
                              void* d_out, int out_size)
{
    const float* x     = (const float*)d_in[0];
    const int*   ei    = (const int*)d_in[1];
    const int*   batch = (const int*)d_in[2];
    int base = (n_in > 3 && in_sizes[3] == 1) ? 4 : 3;

    const float* p[24];
    for (int i = 0; i < 24; i++) p[i] = (const float*)d_in[base + i];
    // b0: 0..7 (Wl1,Wr1,b1,Wl2,Wr2,b2,Wlin,blin); b1: 8..15; bn 16..19; lin1 20,21; lin2 22,23

    const int* src = ei;
    const int* dst = ei + EE;

    void *pm, *pt, *ph1, *ph2, *phb, *phc, *pfill, *ppool;
    cudaGetSymbolAddress(&pm,   g_m);
    cudaGetSymbolAddress(&pt,   g_t);
    cudaGetSymbolAddress(&ph1,  g_h1);
    cudaGetSymbolAddress(&ph2,  g_h2);
    cudaGetSymbolAddress(&phb,  g_hb);
    cudaGetSymbolAddress(&phc,  g_hc);
    cudaGetSymbolAddress(&pfill, g_fill);
    cudaGetSymbolAddress(&ppool, g_pool);

    float* fm  = (float*)pm;
    float* ft  = (float*)pt;
    float* fh1 = (float*)ph1;
    float* fh2 = (float*)ph2;
    float* fhb = (float*)phb;
    float* fhc = (float*)phc;

    cudaFuncSetAttribute(k_combo,  cudaFuncAttributeMaxDynamicSharedMemorySize, GEMM_SMEM);
    cudaFuncSetAttribute(k_gemm1,  cudaFuncAttributeMaxDynamicSharedMemorySize, GEMM_SMEM);
    cudaFuncSetAttribute(k_gemmJK, cudaFuncAttributeMaxDynamicSharedMemorySize, GEMM_SMEM);

    const int ZB = 256;
    // ---- CSR build + pool zero + weight conversion ----
    k_zero_int<<<(NN + ZB - 1) / ZB, ZB>>>((int*)pfill, NN);
    k_count<<<(EE + ZB - 1) / ZB, ZB>>>(dst);
    k_scan<<<1, 1024>>>();
    k_fillcsr<<<(EE + ZB - 1) / ZB, ZB>>>(src, dst);
    k_zero_f<<<(GG * 256 + ZB - 1) / ZB, ZB>>>((float*)ppool, GG * 256);
    // slots: 0 Wl1_0, 1 Wr1_0, 2 Wl2_0, 3 Wr2_0, 4 WlinT_0, 5 WlinB_0,
    //        6 Wl1_1, 7 Wr1_1, 8 Wl2_1, 9 Wr2_1, 10 WlinT_1, 11 WlinB_1
    k_wconv<<<(12 * 16384) / 256, 256>>>(
        p[0], p[1], p[3], p[4], p[6], p[6] + 16384,
        p[8], p[9], p[11], p[12], p[14], p[14] + 16384);

    const int COMBO_BLOCKS = 6250 + NGB;  // 6641

    // ---- block 0, conv1 ----
    k_combo<<<COMBO_BLOCKS, 256, GEMM_SMEM>>>(x, 1, p[2], ft);
    k_gemm1<<<NGB, 256, GEMM_SMEM>>>(fm, 0, ft, fh1);
    // ---- block 0, conv2 ----
    k_combo<<<COMBO_BLOCKS, 256, GEMM_SMEM>>>(fh1, 3, p[5], ft);
    k_gemm1<<<NGB, 256, GEMM_SMEM>>>(fm, 2, ft, fh2);
    // ---- block 0 JK + pool 0 ----
    k_gemmJK<<<NGB, 256, GEMM_SMEM>>>(fh1, 4, fh2, 5, p[7], fhb, batch, 0);

    // ---- block 1, conv1 ----
    k_combo<<<COMBO_BLOCKS, 256, GEMM_SMEM>>>(fhb, 7, p[10], ft);
    k_gemm1<<<NGB, 256, GEMM_SMEM>>>(fm, 6, ft, fh1);
    // ---- block 1, conv2 ----
    k_combo<<<COMBO_BLOCKS, 256, GEMM_SMEM>>>(fh1, 9, p[13], ft);
    k_gemm1<<<NGB, 256, GEMM_SMEM>>>(fm, 8, ft, fh2);
    // ---- block 1 JK + pool 1 ----
    k_gemmJK<<<NGB, 256, GEMM_SMEM>>>(fh1, 10, fh2, 11, p[15], fhc, batch, 128);

    // ---- head ----
    k_head<<<GG, 128>>>(p[16], p[17], p[18], p[19], p[20], p[21], p[22], p[23],
                        (float*)d_out);
}